// round 14
// baseline (speedup 1.0000x reference)
#include <cuda_runtime.h>
#include <cuda_fp16.h>
#include <cstdint>

#define LN_EPS 1e-5f
#define SEQ_L  256
#define KDIM   1024
#define NOUT   128

// ---------------- global scratch (no allocs allowed) ----------------
__device__ __align__(16) __half g_Ah[128 * 8192];   // fp16(x_down)   [n][ij]
__device__ __align__(16) __half g_Bh[128 * 8192];   // fp16(x_down_w) [n][lm]
__device__ __align__(16) __half g_gWh[NOUT * KDIM]; // fp16(gamma*W)  [o][k]
__device__ float g_cb[NOUT];
__device__ __align__(16) __half g_NpH[65536 * KDIM]; // fp16(LN(pair)) [pair][k]

// ---------------- kernel A smem: 2 stages x (2 bufs x [32 n x 272 B]) ------
#define A_STAGE   17408
#define A_AH 0
#define A_BH 8704
#define OFF_NPH 0
#define SMEM_A_TOTAL 34816

// ---------------- kernel B smem: 3 stages x (Np 4KB + gW 8KB) --------------
// rows 64 B, swizzle c ^ ((r>>1)&3), c in 16B units 0..3
#define S_N 0
#define S_G 4096
#define B_STAGE   12288
#define SMEM_B_TOTAL 36864

__device__ __forceinline__ uint32_t smem_u32(const void* p) {
    uint32_t a;
    asm("{ .reg .u64 t; cvta.to.shared.u64 t, %1; cvt.u32.u64 %0, t; }"
        : "=r"(a) : "l"(p));
    return a;
}
__device__ __forceinline__ void cp16(uint32_t dst, const void* src) {
    asm volatile("cp.async.cg.shared.global [%0], [%1], 16;"
                 :: "r"(dst), "l"(src) : "memory");
}
__device__ __forceinline__ void cp_commit() {
    asm volatile("cp.async.commit_group;" ::: "memory");
}
template <int N> __device__ __forceinline__ void cp_wait() {
    asm volatile("cp.async.wait_group %0;" :: "n"(N) : "memory");
}
__device__ __forceinline__ void ldmx4t(uint32_t* r, uint32_t addr) {
    asm volatile("ldmatrix.sync.aligned.m8n8.x4.trans.shared.b16 {%0,%1,%2,%3}, [%4];"
                 : "=r"(r[0]), "=r"(r[1]), "=r"(r[2]), "=r"(r[3]) : "r"(addr));
}
__device__ __forceinline__ void ldmx2t(uint32_t* r, uint32_t addr) {
    asm volatile("ldmatrix.sync.aligned.m8n8.x2.trans.shared.b16 {%0,%1}, [%2];"
                 : "=r"(r[0]), "=r"(r[1]) : "r"(addr));
}
__device__ __forceinline__ void ldmx4(uint32_t* r, uint32_t addr) {
    asm volatile("ldmatrix.sync.aligned.m8n8.x4.shared.b16 {%0,%1,%2,%3}, [%4];"
                 : "=r"(r[0]), "=r"(r[1]), "=r"(r[2]), "=r"(r[3]) : "r"(addr));
}
__device__ __forceinline__ void mma_f32(float* c, const uint32_t* a, const uint32_t* b) {
    asm volatile(
        "mma.sync.aligned.m16n8k16.row.col.f32.f16.f16.f32 "
        "{%0,%1,%2,%3}, {%4,%5,%6,%7}, {%8,%9}, {%0,%1,%2,%3};"
        : "+f"(c[0]), "+f"(c[1]), "+f"(c[2]), "+f"(c[3])
        : "r"(a[0]), "r"(a[1]), "r"(a[2]), "r"(a[3]), "r"(b[0]), "r"(b[1]));
}

// ---------------- prep: fp32 -> fp16 ----------------
__global__ void prep_all(const float* __restrict__ A, const float* __restrict__ B,
                         const float* __restrict__ gamma, const float* __restrict__ beta,
                         const float* __restrict__ W, const float* __restrict__ b) {
    if (blockIdx.x < 2048) {
        const unsigned v = blockIdx.x * 256 + threadIdx.x;  // float4 index
        const float4* src;
        __half* dh;
        unsigned i;
        if (v < 262144) { src = (const float4*)A; i = v; dh = g_Ah; }
        else            { src = (const float4*)B; i = v - 262144; dh = g_Bh; }
        const float4 x = src[i];
        __half2 h01 = __floats2half2_rn(x.x, x.y);
        __half2 h23 = __floats2half2_rn(x.z, x.w);
        ((uint2*)dh)[i] = make_uint2(*(uint32_t*)&h01, *(uint32_t*)&h23);
    } else {
        const int o = blockIdx.x - 2048;
        const int t = threadIdx.x;
        float s = 0.f;
        for (int k = t; k < KDIM; k += 256) {
            const float wv = W[o * KDIM + k];
            g_gWh[o * KDIM + k] = __float2half_rn(gamma[k] * wv);
            s += beta[k] * wv;
        }
        __shared__ float red[256];
        red[t] = s;
        __syncthreads();
        for (int st = 128; st > 0; st >>= 1) {
            if (t < st) red[t] += red[t + st];
            __syncthreads();
        }
        if (t == 0) g_cb[o] = b[o] + red[0];
    }
}

// ---------------- kernel A: GEMM1 + LN -> g_NpH (2-stage cp.async) ---------
__global__ __launch_bounds__(256, 2)
void coevol_g1_kernel() {
    extern __shared__ char sm[];
    const uint32_t SB = smem_u32(sm);

    const int tid = threadIdx.x;
    const int lane = tid & 31, w = tid >> 5;
    const int bx = blockIdx.x, by = blockIdx.y;

    const int mbase = (w & 3) * 32;
    const int nbase = (w >> 2) * 64;
    float acc[2][8][4];
#pragma unroll
    for (int mt = 0; mt < 2; ++mt)
#pragma unroll
        for (int nt = 0; nt < 8; ++nt)
#pragma unroll
            for (int c = 0; c < 4; ++c) acc[mt][nt][c] = 0.f;

    const int g4 = lane >> 3;
    const int grow = lane & 7;
    const int kadd4 = (g4 >> 1) * 8, madd4 = (g4 & 1) * 8;
    const int kadd2 = (g4 & 1) * 8;

    // staging: 4 cp16/thread/stage. v: buf = v>>9 (AH,BH); r=(v&511)>>4; c=v&15
    auto stage_load = [&](int ch) {
        const uint32_t stg = SB + (uint32_t)(ch & 1) * A_STAGE;
#pragma unroll
        for (int it = 0; it < 4; ++it) {
            const int v = it * 256 + tid;          // 0..1023
            const int buf = v >> 9;
            const int rem = v & 511;
            const int r = rem >> 4, c = rem & 15;
            const size_t srow = (size_t)(ch * 32 + r) * 16384;  // 8192 fp16/row
            const uint32_t dst = stg + (uint32_t)buf * 8704u
                               + (uint32_t)r * 272u + (uint32_t)c * 16u;
            const char* src = (buf == 0)
                ? (const char*)g_Ah + srow + bx * 256 + c * 16
                : (const char*)g_Bh + srow + by * 256 + c * 16;
            cp16(dst, src);
        }
    };

    stage_load(0);
    cp_commit();

    for (int ch = 0; ch < 4; ++ch) {
        cp_wait<0>();
        __syncthreads();
        if (ch < 3) { stage_load(ch + 1); cp_commit(); }

        const uint32_t stg = SB + (uint32_t)(ch & 1) * A_STAGE;
#pragma unroll
        for (int ks = 0; ks < 2; ++ks) {
            uint32_t ah[2][4];
#pragma unroll
            for (int mt = 0; mt < 2; ++mt) {
                const uint32_t aoff = (uint32_t)(ks * 16 + kadd4 + grow) * 272u
                                    + (uint32_t)(mbase + mt * 16 + madd4) * 2u;
                ldmx4t(ah[mt], stg + A_AH + aoff);
            }
#pragma unroll
            for (int nt = 0; nt < 8; ++nt) {
                uint32_t bh[2];
                const uint32_t boff = (uint32_t)(ks * 16 + kadd2 + grow) * 272u
                                    + (uint32_t)(nbase + nt * 8) * 2u;
                ldmx2t(bh, stg + A_BH + boff);
#pragma unroll
                for (int mt = 0; mt < 2; ++mt)
                    mma_f32(acc[mt][nt], ah[mt], bh);
            }
        }
    }
    __syncthreads();  // stage smem reuse for Np staging

    // ---------------- LayerNorm (warp-local) -> Np smem fp16 ----------
    const int i_loc = w & 3;
#pragma unroll
    for (int lb = 0; lb < 2; ++lb) {
        const int l_loc = (w >> 2) * 2 + lb;
        float sum = 0.f, sq = 0.f;
#pragma unroll
        for (int mt = 0; mt < 2; ++mt)
#pragma unroll
            for (int nt4 = 0; nt4 < 4; ++nt4)
#pragma unroll
                for (int c = 0; c < 4; ++c) {
                    const float v = acc[mt][lb * 4 + nt4][c];
                    sum += v;
                    sq = fmaf(v, v, sq);
                }
#pragma unroll
        for (int off = 16; off >= 1; off >>= 1) {
            sum += __shfl_xor_sync(0xffffffffu, sum, off);
            sq  += __shfl_xor_sync(0xffffffffu, sq, off);
        }
        const float mean = sum * (1.f / KDIM);
        const float var  = sq * (1.f / KDIM) - mean * mean;
        const float rstd = rsqrtf(var + LN_EPS);
        const int p = i_loc * 4 + l_loc;
#pragma unroll
        for (int mt = 0; mt < 2; ++mt)
#pragma unroll
            for (int nt4 = 0; nt4 < 4; ++nt4)
#pragma unroll
                for (int cp = 0; cp < 2; ++cp) {
                    const float f0 = (acc[mt][lb * 4 + nt4][cp * 2 + 0] - mean) * rstd;
                    const float f1 = (acc[mt][lb * 4 + nt4][cp * 2 + 1] - mean) * rstd;
                    __half2 h2 = __floats2half2_rn(f0, f1);
                    const int j  = mt * 16 + (lane >> 2) + cp * 8;
                    const int mc = nt4 * 4 + (lane & 3);
                    const int idx = p * 516 + j * 16 + (mc ^ ((j & 3) << 2));
                    *(uint32_t*)(sm + OFF_NPH + idx * 4) = *(uint32_t*)&h2;
                }
    }
    __syncthreads();

    // ---------------- copy Np smem -> global (coalesced) ----------
#pragma unroll
    for (int it = 0; it < 8; ++it) {
        const int v = it * 256 + tid;          // 0..2047 uint4
        const int p = v >> 7;
        const int c4 = v & 127;
        const int wb = c4 * 4;
        const int j = wb >> 4, mc = wb & 15;
        const int sidx = p * 516 + j * 16 + (mc ^ ((j & 3) << 2));
        const uint32_t* s = (const uint32_t*)(sm + OFF_NPH) + sidx;
        uint4 val = make_uint4(s[0], s[1], s[2], s[3]);
        const int gi = bx * 4 + (p >> 2);
        const int gl = by * 4 + (p & 3);
        const size_t pair = (size_t)gi * SEQ_L + gl;
        ((uint4*)g_NpH)[pair * 128 + c4] = val;
    }
}

// ---------------- kernel B: out = NpH . gWh + cb (3-stage cp.async) --------
// Grid 1024: CTA = 64 pairs x 128 o, K = 1024 in 32 chunks of 32.
// 8 warps = 2 (pair) x 4 (o): warp tile 32 pairs x 32 o.
__global__ __launch_bounds__(256, 3)
void coevol_g2_kernel(float* __restrict__ out) {
    extern __shared__ char sm[];
    const uint32_t SB = smem_u32(sm);

    const int tid = threadIdx.x;
    const int lane = tid & 31, w = tid >> 5;
    const int pb = blockIdx.x;             // 64-pair block

    const int mp = (w & 1) * 32;           // warp pair base (within 64)
    const int ob = (w >> 1) * 32;          // warp o base (within 128)

    float acc[2][4][4];
#pragma unroll
    for (int mt = 0; mt < 2; ++mt)
#pragma unroll
        for (int nt = 0; nt < 4; ++nt)
#pragma unroll
            for (int c = 0; c < 4; ++c) acc[mt][nt][c] = 0.f;

    const int rA = lane & 15, cAs = lane >> 4;
    const int rB = ((lane >> 4) << 3) + (lane & 7);
    const int cBs = (lane >> 3) & 1;

    // stage load: 3 cp16/thread. Np rows 64 B (64 rows), gW rows 64 B (128).
    auto stage_load = [&](int ch) {
        const uint32_t stg = SB + (uint32_t)(ch % 3) * B_STAGE;
#pragma unroll
        for (int it = 0; it < 3; ++it) {
            const int v = it * 256 + tid;     // 0..767
            uint32_t dst;
            const char* src;
            if (v < 256) {                    // NpH: r 0..63, c 0..3
                const int r = v >> 2, c = v & 3;
                dst = stg + S_N + (uint32_t)(r * 64 + ((c ^ ((r >> 1) & 3)) << 4));
                src = (const char*)g_NpH + (size_t)(pb * 64 + r) * 2048
                    + ch * 64 + c * 16;
            } else {                          // gWh: r 0..127, c 0..3
                const int g = v - 256;        // 0..511
                const int r = g >> 2, c = g & 3;
                dst = stg + S_G + (uint32_t)(r * 64 + ((c ^ ((r >> 1) & 3)) << 4));
                src = (const char*)g_gWh + (size_t)r * 2048 + ch * 64 + c * 16;
            }
            cp16(dst, src);
        }
    };

    stage_load(0); cp_commit();
    stage_load(1); cp_commit();

    for (int ch = 0; ch < 32; ++ch) {
        if (ch < 31) cp_wait<1>(); else cp_wait<0>();
        __syncthreads();
        if (ch + 2 < 32) { stage_load(ch + 2); cp_commit(); }

        const uint32_t stg = SB + (uint32_t)(ch % 3) * B_STAGE;
#pragma unroll
        for (int ks = 0; ks < 2; ++ks) {
            const int cc = ks * 2;
            uint32_t ah[2][4];
#pragma unroll
            for (int mt = 0; mt < 2; ++mt) {
                const int r = mp + mt * 16 + rA;
                const int c = cc + cAs;
                ldmx4(ah[mt], stg + S_N
                      + (uint32_t)(r * 64 + ((c ^ ((r >> 1) & 3)) << 4)));
            }
#pragma unroll
            for (int n4 = 0; n4 < 2; ++n4) {
                uint32_t bh[4];
                const int r = ob + n4 * 16 + rB;
                const int c = cc + cBs;
                ldmx4(bh, stg + S_G
                      + (uint32_t)(r * 64 + ((c ^ ((r >> 1) & 3)) << 4)));
#pragma unroll
                for (int half = 0; half < 2; ++half) {
                    const int nt = n4 * 2 + half;
#pragma unroll
                    for (int mt = 0; mt < 2; ++mt)
                        mma_f32(acc[mt][nt], ah[mt], bh + half * 2);
                }
            }
        }
    }

    // ---------------- epilogue ----------------
#pragma unroll
    for (int nt = 0; nt < 4; ++nt) {
        const int o0 = ob + nt * 8 + 2 * (lane & 3);
        const float cb0 = g_cb[o0], cb1 = g_cb[o0 + 1];
#pragma unroll
        for (int mt = 0; mt < 2; ++mt) {
            const int r0 = mp + mt * 16 + (lane >> 2);
            const size_t pair0 = (size_t)pb * 64 + r0;
            float2 v0, v1;
            v0.x = acc[mt][nt][0] + cb0;
            v0.y = acc[mt][nt][1] + cb1;
            v1.x = acc[mt][nt][2] + cb0;
            v1.y = acc[mt][nt][3] + cb1;
            *(float2*)&out[pair0 * NOUT + o0] = v0;
            *(float2*)&out[(pair0 + 8) * NOUT + o0] = v1;
        }
    }
}

// ---------------------------------------------------------------------------
extern "C" void kernel_launch(void* const* d_in, const int* in_sizes, int n_in,
                              void* d_out, int out_size) {
    const float* x_down   = (const float*)d_in[0];
    const float* x_down_w = (const float*)d_in[1];
    const float* gamma    = (const float*)d_in[2];
    const float* beta     = (const float*)d_in[3];
    const float* W        = (const float*)d_in[4];
    const float* b        = (const float*)d_in[5];
    float* out = (float*)d_out;

    cudaFuncSetAttribute(coevol_g1_kernel,
                         cudaFuncAttributeMaxDynamicSharedMemorySize, SMEM_A_TOTAL);
    cudaFuncSetAttribute(coevol_g2_kernel,
                         cudaFuncAttributeMaxDynamicSharedMemorySize, SMEM_B_TOTAL);

    prep_all<<<2176, 256>>>(x_down, x_down_w, gamma, beta, W, b);

    dim3 grid1(SEQ_L / 4, SEQ_L / 4);  // 64 x 64
    coevol_g1_kernel<<<grid1, 256, SMEM_A_TOTAL>>>();

    coevol_g2_kernel<<<1024, 256, SMEM_B_TOTAL>>>(out);
}

// round 15
// speedup vs baseline: 1.0124x; 1.0124x over previous
#include <cuda_runtime.h>
#include <cuda_fp16.h>
#include <cstdint>

#define LN_EPS 1e-5f
#define SEQ_L  256
#define KDIM   1024
#define NOUT   128

// ---------------- global scratch (no allocs allowed) ----------------
__device__ __align__(16) __half g_Ah[128 * 8192];   // fp16(x_down)   [n][ij]
__device__ __align__(16) __half g_Bh[128 * 8192];   // fp16(x_down_w) [n][lm]
__device__ __align__(16) __half g_gWh[NOUT * KDIM]; // fp16(gamma*W)  [o][k]
__device__ float g_cb[NOUT];
__device__ __align__(16) __half g_NpH[65536 * KDIM]; // fp16(LN(pair)) [pair][k]

// ---------------- kernel A smem: 2 stages x (2 bufs x [32 n x 272 B]) ------
#define A_STAGE   17408
#define A_AH 0
#define A_BH 8704
#define OFF_NPH 0
#define SMEM_A_TOTAL 34816

// ---------------- kernel B smem: 3 stages x (Np 8KB + gW 8KB) --------------
// rows 64 B, swizzle c ^ ((r>>1)&3), c in 16B units 0..3
#define S_N 0
#define S_G 8192
#define B_STAGE   16384
#define SMEM_B_TOTAL 49152

__device__ __forceinline__ uint32_t smem_u32(const void* p) {
    uint32_t a;
    asm("{ .reg .u64 t; cvta.to.shared.u64 t, %1; cvt.u32.u64 %0, t; }"
        : "=r"(a) : "l"(p));
    return a;
}
__device__ __forceinline__ void cp16(uint32_t dst, const void* src) {
    asm volatile("cp.async.cg.shared.global [%0], [%1], 16;"
                 :: "r"(dst), "l"(src) : "memory");
}
__device__ __forceinline__ void cp_commit() {
    asm volatile("cp.async.commit_group;" ::: "memory");
}
template <int N> __device__ __forceinline__ void cp_wait() {
    asm volatile("cp.async.wait_group %0;" :: "n"(N) : "memory");
}
__device__ __forceinline__ void ldmx4t(uint32_t* r, uint32_t addr) {
    asm volatile("ldmatrix.sync.aligned.m8n8.x4.trans.shared.b16 {%0,%1,%2,%3}, [%4];"
                 : "=r"(r[0]), "=r"(r[1]), "=r"(r[2]), "=r"(r[3]) : "r"(addr));
}
__device__ __forceinline__ void ldmx2t(uint32_t* r, uint32_t addr) {
    asm volatile("ldmatrix.sync.aligned.m8n8.x2.trans.shared.b16 {%0,%1}, [%2];"
                 : "=r"(r[0]), "=r"(r[1]) : "r"(addr));
}
__device__ __forceinline__ void ldmx4(uint32_t* r, uint32_t addr) {
    asm volatile("ldmatrix.sync.aligned.m8n8.x4.shared.b16 {%0,%1,%2,%3}, [%4];"
                 : "=r"(r[0]), "=r"(r[1]), "=r"(r[2]), "=r"(r[3]) : "r"(addr));
}
__device__ __forceinline__ void mma_f32(float* c, const uint32_t* a, const uint32_t* b) {
    asm volatile(
        "mma.sync.aligned.m16n8k16.row.col.f32.f16.f16.f32 "
        "{%0,%1,%2,%3}, {%4,%5,%6,%7}, {%8,%9}, {%0,%1,%2,%3};"
        : "+f"(c[0]), "+f"(c[1]), "+f"(c[2]), "+f"(c[3])
        : "r"(a[0]), "r"(a[1]), "r"(a[2]), "r"(a[3]), "r"(b[0]), "r"(b[1]));
}

// ---------------- prep: fp32 -> fp16 (8 float4/thread for MLP) -------------
__global__ void prep_all(const float* __restrict__ A, const float* __restrict__ B,
                         const float* __restrict__ gamma, const float* __restrict__ beta,
                         const float* __restrict__ W, const float* __restrict__ b) {
    if (blockIdx.x < 256) {
        // conversions: 524288 float4 total; 256 blocks x 256 threads x 8 each
#pragma unroll
        for (int it = 0; it < 8; ++it) {
            const unsigned v = blockIdx.x * 2048 + it * 256 + threadIdx.x;
            const float4* src;
            __half* dh;
            unsigned i;
            if (v < 262144) { src = (const float4*)A; i = v; dh = g_Ah; }
            else            { src = (const float4*)B; i = v - 262144; dh = g_Bh; }
            const float4 x = src[i];
            __half2 h01 = __floats2half2_rn(x.x, x.y);
            __half2 h23 = __floats2half2_rn(x.z, x.w);
            ((uint2*)dh)[i] = make_uint2(*(uint32_t*)&h01, *(uint32_t*)&h23);
        }
    } else {
        const int o = blockIdx.x - 256;    // 128 blocks
        const int t = threadIdx.x;
        float s = 0.f;
        for (int k = t; k < KDIM; k += 256) {
            const float wv = W[o * KDIM + k];
            g_gWh[o * KDIM + k] = __float2half_rn(gamma[k] * wv);
            s += beta[k] * wv;
        }
        __shared__ float red[256];
        red[t] = s;
        __syncthreads();
        for (int st = 128; st > 0; st >>= 1) {
            if (t < st) red[t] += red[t + st];
            __syncthreads();
        }
        if (t == 0) g_cb[o] = b[o] + red[0];
    }
}

// ---------------- kernel A: GEMM1 + LN -> g_NpH (2-stage cp.async) ---------
__global__ __launch_bounds__(256, 2)
void coevol_g1_kernel() {
    extern __shared__ char sm[];
    const uint32_t SB = smem_u32(sm);

    const int tid = threadIdx.x;
    const int lane = tid & 31, w = tid >> 5;
    const int bx = blockIdx.x, by = blockIdx.y;

    const int mbase = (w & 3) * 32;
    const int nbase = (w >> 2) * 64;
    float acc[2][8][4];
#pragma unroll
    for (int mt = 0; mt < 2; ++mt)
#pragma unroll
        for (int nt = 0; nt < 8; ++nt)
#pragma unroll
            for (int c = 0; c < 4; ++c) acc[mt][nt][c] = 0.f;

    const int g4 = lane >> 3;
    const int grow = lane & 7;
    const int kadd4 = (g4 >> 1) * 8, madd4 = (g4 & 1) * 8;
    const int kadd2 = (g4 & 1) * 8;

    // staging: 4 cp16/thread/stage. v: buf = v>>9 (AH,BH); r=(v&511)>>4; c=v&15
    auto stage_load = [&](int ch) {
        const uint32_t stg = SB + (uint32_t)(ch & 1) * A_STAGE;
#pragma unroll
        for (int it = 0; it < 4; ++it) {
            const int v = it * 256 + tid;          // 0..1023
            const int buf = v >> 9;
            const int rem = v & 511;
            const int r = rem >> 4, c = rem & 15;
            const size_t srow = (size_t)(ch * 32 + r) * 16384;  // 8192 fp16/row
            const uint32_t dst = stg + (uint32_t)buf * 8704u
                               + (uint32_t)r * 272u + (uint32_t)c * 16u;
            const char* src = (buf == 0)
                ? (const char*)g_Ah + srow + bx * 256 + c * 16
                : (const char*)g_Bh + srow + by * 256 + c * 16;
            cp16(dst, src);
        }
    };

    stage_load(0);
    cp_commit();

    for (int ch = 0; ch < 4; ++ch) {
        cp_wait<0>();
        __syncthreads();
        if (ch < 3) { stage_load(ch + 1); cp_commit(); }

        const uint32_t stg = SB + (uint32_t)(ch & 1) * A_STAGE;
#pragma unroll
        for (int ks = 0; ks < 2; ++ks) {
            uint32_t ah[2][4];
#pragma unroll
            for (int mt = 0; mt < 2; ++mt) {
                const uint32_t aoff = (uint32_t)(ks * 16 + kadd4 + grow) * 272u
                                    + (uint32_t)(mbase + mt * 16 + madd4) * 2u;
                ldmx4t(ah[mt], stg + A_AH + aoff);
            }
#pragma unroll
            for (int nt = 0; nt < 8; ++nt) {
                uint32_t bh[2];
                const uint32_t boff = (uint32_t)(ks * 16 + kadd2 + grow) * 272u
                                    + (uint32_t)(nbase + nt * 8) * 2u;
                ldmx2t(bh, stg + A_BH + boff);
#pragma unroll
                for (int mt = 0; mt < 2; ++mt)
                    mma_f32(acc[mt][nt], ah[mt], bh);
            }
        }
    }
    __syncthreads();  // stage smem reuse for Np staging

    // ---------------- LayerNorm (warp-local) -> Np smem fp16 ----------
    const int i_loc = w & 3;
#pragma unroll
    for (int lb = 0; lb < 2; ++lb) {
        const int l_loc = (w >> 2) * 2 + lb;
        float sum = 0.f, sq = 0.f;
#pragma unroll
        for (int mt = 0; mt < 2; ++mt)
#pragma unroll
            for (int nt4 = 0; nt4 < 4; ++nt4)
#pragma unroll
                for (int c = 0; c < 4; ++c) {
                    const float v = acc[mt][lb * 4 + nt4][c];
                    sum += v;
                    sq = fmaf(v, v, sq);
                }
#pragma unroll
        for (int off = 16; off >= 1; off >>= 1) {
            sum += __shfl_xor_sync(0xffffffffu, sum, off);
            sq  += __shfl_xor_sync(0xffffffffu, sq, off);
        }
        const float mean = sum * (1.f / KDIM);
        const float var  = sq * (1.f / KDIM) - mean * mean;
        const float rstd = rsqrtf(var + LN_EPS);
        const int p = i_loc * 4 + l_loc;
#pragma unroll
        for (int mt = 0; mt < 2; ++mt)
#pragma unroll
            for (int nt4 = 0; nt4 < 4; ++nt4)
#pragma unroll
                for (int cp = 0; cp < 2; ++cp) {
                    const float f0 = (acc[mt][lb * 4 + nt4][cp * 2 + 0] - mean) * rstd;
                    const float f1 = (acc[mt][lb * 4 + nt4][cp * 2 + 1] - mean) * rstd;
                    __half2 h2 = __floats2half2_rn(f0, f1);
                    const int j  = mt * 16 + (lane >> 2) + cp * 8;
                    const int mc = nt4 * 4 + (lane & 3);
                    const int idx = p * 516 + j * 16 + (mc ^ ((j & 3) << 2));
                    *(uint32_t*)(sm + OFF_NPH + idx * 4) = *(uint32_t*)&h2;
                }
    }
    __syncthreads();

    // ---------------- copy Np smem -> global (coalesced) ----------
#pragma unroll
    for (int it = 0; it < 8; ++it) {
        const int v = it * 256 + tid;          // 0..2047 uint4
        const int p = v >> 7;
        const int c4 = v & 127;
        const int wb = c4 * 4;
        const int j = wb >> 4, mc = wb & 15;
        const int sidx = p * 516 + j * 16 + (mc ^ ((j & 3) << 2));
        const uint32_t* s = (const uint32_t*)(sm + OFF_NPH) + sidx;
        uint4 val = make_uint4(s[0], s[1], s[2], s[3]);
        const int gi = bx * 4 + (p >> 2);
        const int gl = by * 4 + (p & 3);
        const size_t pair = (size_t)gi * SEQ_L + gl;
        ((uint4*)g_NpH)[pair * 128 + c4] = val;
    }
}

// ---------------- kernel B: out = NpH . gWh + cb (3-stage cp.async) --------
// Grid 512: CTA = 128 pairs x 128 o, K = 1024 in 32 chunks of 32.
__global__ __launch_bounds__(256, 2)
void coevol_g2_kernel(float* __restrict__ out) {
    extern __shared__ char sm[];
    const uint32_t SB = smem_u32(sm);

    const int tid = threadIdx.x;
    const int lane = tid & 31, w = tid >> 5;
    const int pb = blockIdx.x;

    const int mp = (w & 3) * 32;
    const int ob = (w >> 2) * 64;

    float acc[2][8][4];
#pragma unroll
    for (int mt = 0; mt < 2; ++mt)
#pragma unroll
        for (int nt = 0; nt < 8; ++nt)
#pragma unroll
            for (int c = 0; c < 4; ++c) acc[mt][nt][c] = 0.f;

    const int rA = lane & 15, cAs = lane >> 4;
    const int rB = ((lane >> 4) << 3) + (lane & 7);
    const int cBs = (lane >> 3) & 1;

    // stage load: 4 cp16/thread. Np and gW rows 64 B, swizzle c^((r>>1)&3).
    auto stage_load = [&](int ch) {
        const uint32_t stg = SB + (uint32_t)(ch % 3) * B_STAGE;
#pragma unroll
        for (int it = 0; it < 4; ++it) {
            const int v = it * 256 + tid;     // 0..1023
            uint32_t dst;
            const char* src;
            if (v < 512) {                    // NpH
                const int r = v >> 2, c = v & 3;
                dst = stg + S_N + (uint32_t)(r * 64 + ((c ^ ((r >> 1) & 3)) << 4));
                src = (const char*)g_NpH + (size_t)(pb * 128 + r) * 2048
                    + ch * 64 + c * 16;
            } else {                          // gWh
                const int g = v - 512;        // 0..511
                const int r = g >> 2, c = g & 3;
                dst = stg + S_G + (uint32_t)(r * 64 + ((c ^ ((r >> 1) & 3)) << 4));
                src = (const char*)g_gWh + (size_t)r * 2048 + ch * 64 + c * 16;
            }
            cp16(dst, src);
        }
    };

    stage_load(0); cp_commit();
    stage_load(1); cp_commit();

    for (int ch = 0; ch < 32; ++ch) {
        if (ch < 31) cp_wait<1>(); else cp_wait<0>();
        __syncthreads();
        if (ch + 2 < 32) { stage_load(ch + 2); cp_commit(); }

        const uint32_t stg = SB + (uint32_t)(ch % 3) * B_STAGE;
#pragma unroll
        for (int ks = 0; ks < 2; ++ks) {
            const int cc = ks * 2;
            uint32_t ah[2][4];
#pragma unroll
            for (int mt = 0; mt < 2; ++mt) {
                const int r = mp + mt * 16 + rA;
                const int c = cc + cAs;
                ldmx4(ah[mt], stg + S_N
                      + (uint32_t)(r * 64 + ((c ^ ((r >> 1) & 3)) << 4)));
            }
#pragma unroll
            for (int n4 = 0; n4 < 4; ++n4) {
                uint32_t bh[4];
                const int r = ob + n4 * 16 + rB;
                const int c = cc + cBs;
                ldmx4(bh, stg + S_G
                      + (uint32_t)(r * 64 + ((c ^ ((r >> 1) & 3)) << 4)));
#pragma unroll
                for (int half = 0; half < 2; ++half) {
                    const int nt = n4 * 2 + half;
#pragma unroll
                    for (int mt = 0; mt < 2; ++mt)
                        mma_f32(acc[mt][nt], ah[mt], bh + half * 2);
                }
            }
        }
    }

    // ---------------- epilogue ----------------
#pragma unroll
    for (int nt = 0; nt < 8; ++nt) {
        const int o0 = ob + nt * 8 + 2 * (lane & 3);
        const float cb0 = g_cb[o0], cb1 = g_cb[o0 + 1];
#pragma unroll
        for (int mt = 0; mt < 2; ++mt) {
            const int r0 = mp + mt * 16 + (lane >> 2);
            const size_t pair0 = (size_t)pb * 128 + r0;
            float2 v0, v1;
            v0.x = acc[mt][nt][0] + cb0;
            v0.y = acc[mt][nt][1] + cb1;
            v1.x = acc[mt][nt][2] + cb0;
            v1.y = acc[mt][nt][3] + cb1;
            *(float2*)&out[pair0 * NOUT + o0] = v0;
            *(float2*)&out[(pair0 + 8) * NOUT + o0] = v1;
        }
    }
}

// ---------------------------------------------------------------------------
extern "C" void kernel_launch(void* const* d_in, const int* in_sizes, int n_in,
                              void* d_out, int out_size) {
    const float* x_down   = (const float*)d_in[0];
    const float* x_down_w = (const float*)d_in[1];
    const float* gamma    = (const float*)d_in[2];
    const float* beta     = (const float*)d_in[3];
    const float* W        = (const float*)d_in[4];
    const float* b        = (const float*)d_in[5];
    float* out = (float*)d_out;

    cudaFuncSetAttribute(coevol_g1_kernel,
                         cudaFuncAttributeMaxDynamicSharedMemorySize, SMEM_A_TOTAL);
    cudaFuncSetAttribute(coevol_g2_kernel,
                         cudaFuncAttributeMaxDynamicSharedMemorySize, SMEM_B_TOTAL);

    prep_all<<<384, 256>>>(x_down, x_down_w, gamma, beta, W, b);

    dim3 grid1(SEQ_L / 4, SEQ_L / 4);  // 64 x 64
    coevol_g1_kernel<<<grid1, 256, SMEM_A_TOTAL>>>();

    coevol_g2_kernel<<<512, 256, SMEM_B_TOTAL>>>(out);
}

// round 16
// speedup vs baseline: 1.0439x; 1.0311x over previous
#include <cuda_runtime.h>
#include <cuda_fp16.h>
#include <cstdint>

#define LN_EPS 1e-5f
#define SEQ_L  256
#define KDIM   1024
#define NOUT   128

// ---------------- global scratch (no allocs allowed) ----------------
__device__ __align__(16) __half g_Ah[128 * 8192];   // fp16(x_down)   [n][ij]
__device__ __align__(16) __half g_Bh[128 * 8192];   // fp16(x_down_w) [n][lm]
__device__ __align__(16) __half g_gWh[NOUT * KDIM]; // fp16(gamma*W)  [o][k]
__device__ float g_cb[NOUT];
__device__ __align__(16) __half g_NpH[65536 * KDIM]; // fp16(LN(pair)) [pair][k]

// ---------------- kernel A smem: 2 stages x (2 bufs x [32 n x 272 B]) ------
#define A_STAGE   17408
#define A_AH 0
#define A_BH 8704
#define OFF_NPH 0
#define SMEM_A_TOTAL 34816

// ---------------- kernel B smem: 3 stages x (Np 16KB + gW 16KB) ------------
// rows 128 B, swizzle c ^ (r&7), c in 16B units 0..7 (K-chunk = 64)
#define S_N 0
#define S_G 16384
#define B_STAGE   32768
#define SMEM_B_TOTAL 98304

__device__ __forceinline__ uint32_t smem_u32(const void* p) {
    uint32_t a;
    asm("{ .reg .u64 t; cvta.to.shared.u64 t, %1; cvt.u32.u64 %0, t; }"
        : "=r"(a) : "l"(p));
    return a;
}
__device__ __forceinline__ void cp16(uint32_t dst, const void* src) {
    asm volatile("cp.async.cg.shared.global [%0], [%1], 16;"
                 :: "r"(dst), "l"(src) : "memory");
}
__device__ __forceinline__ void cp_commit() {
    asm volatile("cp.async.commit_group;" ::: "memory");
}
template <int N> __device__ __forceinline__ void cp_wait() {
    asm volatile("cp.async.wait_group %0;" :: "n"(N) : "memory");
}
__device__ __forceinline__ void ldmx4t(uint32_t* r, uint32_t addr) {
    asm volatile("ldmatrix.sync.aligned.m8n8.x4.trans.shared.b16 {%0,%1,%2,%3}, [%4];"
                 : "=r"(r[0]), "=r"(r[1]), "=r"(r[2]), "=r"(r[3]) : "r"(addr));
}
__device__ __forceinline__ void ldmx2t(uint32_t* r, uint32_t addr) {
    asm volatile("ldmatrix.sync.aligned.m8n8.x2.trans.shared.b16 {%0,%1}, [%2];"
                 : "=r"(r[0]), "=r"(r[1]) : "r"(addr));
}
__device__ __forceinline__ void ldmx4(uint32_t* r, uint32_t addr) {
    asm volatile("ldmatrix.sync.aligned.m8n8.x4.shared.b16 {%0,%1,%2,%3}, [%4];"
                 : "=r"(r[0]), "=r"(r[1]), "=r"(r[2]), "=r"(r[3]) : "r"(addr));
}
__device__ __forceinline__ void mma_f32(float* c, const uint32_t* a, const uint32_t* b) {
    asm volatile(
        "mma.sync.aligned.m16n8k16.row.col.f32.f16.f16.f32 "
        "{%0,%1,%2,%3}, {%4,%5,%6,%7}, {%8,%9}, {%0,%1,%2,%3};"
        : "+f"(c[0]), "+f"(c[1]), "+f"(c[2]), "+f"(c[3])
        : "r"(a[0]), "r"(a[1]), "r"(a[2]), "r"(a[3]), "r"(b[0]), "r"(b[1]));
}

// ---------------- prep: fp32 -> fp16 (512 blocks x 4 float4/thread) --------
__global__ void prep_all(const float* __restrict__ A, const float* __restrict__ B,
                         const float* __restrict__ gamma, const float* __restrict__ beta,
                         const float* __restrict__ W, const float* __restrict__ b) {
    if (blockIdx.x < 512) {
        // conversions: 524288 float4 total; 512 blocks x 256 threads x 4 each
#pragma unroll
        for (int it = 0; it < 4; ++it) {
            const unsigned v = blockIdx.x * 1024 + it * 256 + threadIdx.x;
            const float4* src;
            __half* dh;
            unsigned i;
            if (v < 262144) { src = (const float4*)A; i = v; dh = g_Ah; }
            else            { src = (const float4*)B; i = v - 262144; dh = g_Bh; }
            const float4 x = src[i];
            __half2 h01 = __floats2half2_rn(x.x, x.y);
            __half2 h23 = __floats2half2_rn(x.z, x.w);
            ((uint2*)dh)[i] = make_uint2(*(uint32_t*)&h01, *(uint32_t*)&h23);
        }
    } else {
        const int o = blockIdx.x - 512;    // 128 blocks
        const int t = threadIdx.x;
        float s = 0.f;
        for (int k = t; k < KDIM; k += 256) {
            const float wv = W[o * KDIM + k];
            g_gWh[o * KDIM + k] = __float2half_rn(gamma[k] * wv);
            s += beta[k] * wv;
        }
        __shared__ float red[256];
        red[t] = s;
        __syncthreads();
        for (int st = 128; st > 0; st >>= 1) {
            if (t < st) red[t] += red[t + st];
            __syncthreads();
        }
        if (t == 0) g_cb[o] = b[o] + red[0];
    }
}

// ---------------- kernel A: GEMM1 + LN -> g_NpH (2-stage cp.async) ---------
__global__ __launch_bounds__(256, 2)
void coevol_g1_kernel() {
    extern __shared__ char sm[];
    const uint32_t SB = smem_u32(sm);

    const int tid = threadIdx.x;
    const int lane = tid & 31, w = tid >> 5;
    const int bx = blockIdx.x, by = blockIdx.y;

    const int mbase = (w & 3) * 32;
    const int nbase = (w >> 2) * 64;
    float acc[2][8][4];
#pragma unroll
    for (int mt = 0; mt < 2; ++mt)
#pragma unroll
        for (int nt = 0; nt < 8; ++nt)
#pragma unroll
            for (int c = 0; c < 4; ++c) acc[mt][nt][c] = 0.f;

    const int g4 = lane >> 3;
    const int grow = lane & 7;
    const int kadd4 = (g4 >> 1) * 8, madd4 = (g4 & 1) * 8;
    const int kadd2 = (g4 & 1) * 8;

    // staging: 4 cp16/thread/stage. v: buf = v>>9 (AH,BH); r=(v&511)>>4; c=v&15
    auto stage_load = [&](int ch) {
        const uint32_t stg = SB + (uint32_t)(ch & 1) * A_STAGE;
#pragma unroll
        for (int it = 0; it < 4; ++it) {
            const int v = it * 256 + tid;          // 0..1023
            const int buf = v >> 9;
            const int rem = v & 511;
            const int r = rem >> 4, c = rem & 15;
            const size_t srow = (size_t)(ch * 32 + r) * 16384;  // 8192 fp16/row
            const uint32_t dst = stg + (uint32_t)buf * 8704u
                               + (uint32_t)r * 272u + (uint32_t)c * 16u;
            const char* src = (buf == 0)
                ? (const char*)g_Ah + srow + bx * 256 + c * 16
                : (const char*)g_Bh + srow + by * 256 + c * 16;
            cp16(dst, src);
        }
    };

    stage_load(0);
    cp_commit();

    for (int ch = 0; ch < 4; ++ch) {
        cp_wait<0>();
        __syncthreads();
        if (ch < 3) { stage_load(ch + 1); cp_commit(); }

        const uint32_t stg = SB + (uint32_t)(ch & 1) * A_STAGE;
#pragma unroll
        for (int ks = 0; ks < 2; ++ks) {
            uint32_t ah[2][4];
#pragma unroll
            for (int mt = 0; mt < 2; ++mt) {
                const uint32_t aoff = (uint32_t)(ks * 16 + kadd4 + grow) * 272u
                                    + (uint32_t)(mbase + mt * 16 + madd4) * 2u;
                ldmx4t(ah[mt], stg + A_AH + aoff);
            }
#pragma unroll
            for (int nt = 0; nt < 8; ++nt) {
                uint32_t bh[2];
                const uint32_t boff = (uint32_t)(ks * 16 + kadd2 + grow) * 272u
                                    + (uint32_t)(nbase + nt * 8) * 2u;
                ldmx2t(bh, stg + A_BH + boff);
#pragma unroll
                for (int mt = 0; mt < 2; ++mt)
                    mma_f32(acc[mt][nt], ah[mt], bh);
            }
        }
    }
    __syncthreads();  // stage smem reuse for Np staging

    // ---------------- LayerNorm (warp-local) -> Np smem fp16 ----------
    const int i_loc = w & 3;
#pragma unroll
    for (int lb = 0; lb < 2; ++lb) {
        const int l_loc = (w >> 2) * 2 + lb;
        float sum = 0.f, sq = 0.f;
#pragma unroll
        for (int mt = 0; mt < 2; ++mt)
#pragma unroll
            for (int nt4 = 0; nt4 < 4; ++nt4)
#pragma unroll
                for (int c = 0; c < 4; ++c) {
                    const float v = acc[mt][lb * 4 + nt4][c];
                    sum += v;
                    sq = fmaf(v, v, sq);
                }
#pragma unroll
        for (int off = 16; off >= 1; off >>= 1) {
            sum += __shfl_xor_sync(0xffffffffu, sum, off);
            sq  += __shfl_xor_sync(0xffffffffu, sq, off);
        }
        const float mean = sum * (1.f / KDIM);
        const float var  = sq * (1.f / KDIM) - mean * mean;
        const float rstd = rsqrtf(var + LN_EPS);
        const int p = i_loc * 4 + l_loc;
#pragma unroll
        for (int mt = 0; mt < 2; ++mt)
#pragma unroll
            for (int nt4 = 0; nt4 < 4; ++nt4)
#pragma unroll
                for (int cp = 0; cp < 2; ++cp) {
                    const float f0 = (acc[mt][lb * 4 + nt4][cp * 2 + 0] - mean) * rstd;
                    const float f1 = (acc[mt][lb * 4 + nt4][cp * 2 + 1] - mean) * rstd;
                    __half2 h2 = __floats2half2_rn(f0, f1);
                    const int j  = mt * 16 + (lane >> 2) + cp * 8;
                    const int mc = nt4 * 4 + (lane & 3);
                    const int idx = p * 516 + j * 16 + (mc ^ ((j & 3) << 2));
                    *(uint32_t*)(sm + OFF_NPH + idx * 4) = *(uint32_t*)&h2;
                }
    }
    __syncthreads();

    // ---------------- copy Np smem -> global (coalesced) ----------
#pragma unroll
    for (int it = 0; it < 8; ++it) {
        const int v = it * 256 + tid;          // 0..2047 uint4
        const int p = v >> 7;
        const int c4 = v & 127;
        const int wb = c4 * 4;
        const int j = wb >> 4, mc = wb & 15;
        const int sidx = p * 516 + j * 16 + (mc ^ ((j & 3) << 2));
        const uint32_t* s = (const uint32_t*)(sm + OFF_NPH) + sidx;
        uint4 val = make_uint4(s[0], s[1], s[2], s[3]);
        const int gi = bx * 4 + (p >> 2);
        const int gl = by * 4 + (p & 3);
        const size_t pair = (size_t)gi * SEQ_L + gl;
        ((uint4*)g_NpH)[pair * 128 + c4] = val;
    }
}

// ---------------- kernel B: out = NpH . gWh + cb (3-stage cp.async) --------
// Grid 512: CTA = 128 pairs x 128 o, K = 1024 in 16 chunks of 64.
__global__ __launch_bounds__(256, 2)
void coevol_g2_kernel(float* __restrict__ out) {
    extern __shared__ char sm[];
    const uint32_t SB = smem_u32(sm);

    const int tid = threadIdx.x;
    const int lane = tid & 31, w = tid >> 5;
    const int pb = blockIdx.x;

    const int mp = (w & 3) * 32;
    const int ob = (w >> 2) * 64;

    float acc[2][8][4];
#pragma unroll
    for (int mt = 0; mt < 2; ++mt)
#pragma unroll
        for (int nt = 0; nt < 8; ++nt)
#pragma unroll
            for (int c = 0; c < 4; ++c) acc[mt][nt][c] = 0.f;

    const int rA = lane & 15, cAs = lane >> 4;
    const int rB = ((lane >> 4) << 3) + (lane & 7);
    const int cBs = (lane >> 3) & 1;

    // stage load: 8 cp16/thread. Np and gW rows 128 B, swizzle c^(r&7).
    auto stage_load = [&](int ch) {
        const uint32_t stg = SB + (uint32_t)(ch % 3) * B_STAGE;
#pragma unroll
        for (int it = 0; it < 8; ++it) {
            const int v = it * 256 + tid;     // 0..2047
            const int buf = v >> 10;          // 0 = Np, 1 = gW
            const int rem = v & 1023;
            const int r = rem >> 3, c = rem & 7;
            const uint32_t dst = stg + (uint32_t)buf * 16384u
                               + (uint32_t)(r * 128) + (uint32_t)((c ^ (r & 7)) << 4);
            const char* src = (buf == 0)
                ? (const char*)g_NpH + (size_t)(pb * 128 + r) * 2048 + ch * 128 + c * 16
                : (const char*)g_gWh + (size_t)r * 2048 + ch * 128 + c * 16;
            cp16(dst, src);
        }
    };

    stage_load(0); cp_commit();
    stage_load(1); cp_commit();

    for (int ch = 0; ch < 16; ++ch) {
        if (ch < 15) cp_wait<1>(); else cp_wait<0>();
        __syncthreads();
        if (ch + 2 < 16) { stage_load(ch + 2); cp_commit(); }

        const uint32_t stg = SB + (uint32_t)(ch % 3) * B_STAGE;
#pragma unroll
        for (int ks = 0; ks < 4; ++ks) {
            const int cc = ks * 2;
            uint32_t ah[2][4];
#pragma unroll
            for (int mt = 0; mt < 2; ++mt) {
                const int r = mp + mt * 16 + rA;
                const int c = cc + cAs;
                ldmx4(ah[mt], stg + S_N
                      + (uint32_t)(r * 128 + ((c ^ (r & 7)) << 4)));
            }
#pragma unroll
            for (int n4 = 0; n4 < 4; ++n4) {
                uint32_t bh[4];
                const int r = ob + n4 * 16 + rB;
                const int c = cc + cBs;
                ldmx4(bh, stg + S_G
                      + (uint32_t)(r * 128 + ((c ^ (r & 7)) << 4)));
#pragma unroll
                for (int half = 0; half < 2; ++half) {
                    const int nt = n4 * 2 + half;
#pragma unroll
                    for (int mt = 0; mt < 2; ++mt)
                        mma_f32(acc[mt][nt], ah[mt], bh + half * 2);
                }
            }
        }
    }

    // ---------------- epilogue ----------------
#pragma unroll
    for (int nt = 0; nt < 8; ++nt) {
        const int o0 = ob + nt * 8 + 2 * (lane & 3);
        const float cb0 = g_cb[o0], cb1 = g_cb[o0 + 1];
#pragma unroll
        for (int mt = 0; mt < 2; ++mt) {
            const int r0 = mp + mt * 16 + (lane >> 2);
            const size_t pair0 = (size_t)pb * 128 + r0;
            float2 v0, v1;
            v0.x = acc[mt][nt][0] + cb0;
            v0.y = acc[mt][nt][1] + cb1;
            v1.x = acc[mt][nt][2] + cb0;
            v1.y = acc[mt][nt][3] + cb1;
            *(float2*)&out[pair0 * NOUT + o0] = v0;
            *(float2*)&out[(pair0 + 8) * NOUT + o0] = v1;
        }
    }
}

// ---------------------------------------------------------------------------
extern "C" void kernel_launch(void* const* d_in, const int* in_sizes, int n_in,
                              void* d_out, int out_size) {
    const float* x_down   = (const float*)d_in[0];
    const float* x_down_w = (const float*)d_in[1];
    const float* gamma    = (const float*)d_in[2];
    const float* beta     = (const float*)d_in[3];
    const float* W        = (const float*)d_in[4];
    const float* b        = (const float*)d_in[5];
    float* out = (float*)d_out;

    cudaFuncSetAttribute(coevol_g1_kernel,
                         cudaFuncAttributeMaxDynamicSharedMemorySize, SMEM_A_TOTAL);
    cudaFuncSetAttribute(coevol_g2_kernel,
                         cudaFuncAttributeMaxDynamicSharedMemorySize, SMEM_B_TOTAL);

    prep_all<<<640, 256>>>(x_down, x_down_w, gamma, beta, W, b);

    dim3 grid1(SEQ_L / 4, SEQ_L / 4);  // 64 x 64
    coevol_g1_kernel<<<grid1, 256, SMEM_A_TOTAL>>>();

    coevol_g2_kernel<<<512, 256, SMEM_B_TOTAL>>>(out);
}

// round 17
// speedup vs baseline: 1.0872x; 1.0414x over previous
#include <cuda_runtime.h>
#include <cuda_fp16.h>
#include <cstdint>

#define LN_EPS 1e-5f
#define SEQ_L  256
#define KDIM   1024
#define NOUT   128

// ---------------- global scratch (no allocs allowed) ----------------
__device__ __align__(16) __half g_Ah[128 * 8192];   // fp16(x_down)   [n][ij]
__device__ __align__(16) __half g_Bh[128 * 8192];   // fp16(x_down_w) [n][lm]
__device__ __align__(16) __half g_gWh[NOUT * KDIM]; // fp16(gamma*W)  [o][k]
__device__ float g_cb[NOUT];
__device__ __align__(16) __half g_NpH[65536 * KDIM]; // fp16(LN(pair)) [pair][k]

// ---------------- kernel A smem: 2 stages x (2 bufs x [64 n x 272 B]) ------
#define A_STAGE   34816
#define A_AH 0
#define A_BH 17408
#define OFF_NPH 0
#define SMEM_A_TOTAL 69632

// ---------------- kernel B smem: 3 stages x (Np 16KB + gW 16KB) ------------
// rows 128 B, swizzle c ^ (r&7), c in 16B units 0..7 (K-chunk = 64)
#define S_N 0
#define S_G 16384
#define B_STAGE   32768
#define SMEM_B_TOTAL 98304

__device__ __forceinline__ uint32_t smem_u32(const void* p) {
    uint32_t a;
    asm("{ .reg .u64 t; cvta.to.shared.u64 t, %1; cvt.u32.u64 %0, t; }"
        : "=r"(a) : "l"(p));
    return a;
}
__device__ __forceinline__ void cp16(uint32_t dst, const void* src) {
    asm volatile("cp.async.cg.shared.global [%0], [%1], 16;"
                 :: "r"(dst), "l"(src) : "memory");
}
__device__ __forceinline__ void cp_commit() {
    asm volatile("cp.async.commit_group;" ::: "memory");
}
template <int N> __device__ __forceinline__ void cp_wait() {
    asm volatile("cp.async.wait_group %0;" :: "n"(N) : "memory");
}
__device__ __forceinline__ void ldmx4t(uint32_t* r, uint32_t addr) {
    asm volatile("ldmatrix.sync.aligned.m8n8.x4.trans.shared.b16 {%0,%1,%2,%3}, [%4];"
                 : "=r"(r[0]), "=r"(r[1]), "=r"(r[2]), "=r"(r[3]) : "r"(addr));
}
__device__ __forceinline__ void ldmx2t(uint32_t* r, uint32_t addr) {
    asm volatile("ldmatrix.sync.aligned.m8n8.x2.trans.shared.b16 {%0,%1}, [%2];"
                 : "=r"(r[0]), "=r"(r[1]) : "r"(addr));
}
__device__ __forceinline__ void ldmx4(uint32_t* r, uint32_t addr) {
    asm volatile("ldmatrix.sync.aligned.m8n8.x4.shared.b16 {%0,%1,%2,%3}, [%4];"
                 : "=r"(r[0]), "=r"(r[1]), "=r"(r[2]), "=r"(r[3]) : "r"(addr));
}
__device__ __forceinline__ void mma_f32(float* c, const uint32_t* a, const uint32_t* b) {
    asm volatile(
        "mma.sync.aligned.m16n8k16.row.col.f32.f16.f16.f32 "
        "{%0,%1,%2,%3}, {%4,%5,%6,%7}, {%8,%9}, {%0,%1,%2,%3};"
        : "+f"(c[0]), "+f"(c[1]), "+f"(c[2]), "+f"(c[3])
        : "r"(a[0]), "r"(a[1]), "r"(a[2]), "r"(a[3]), "r"(b[0]), "r"(b[1]));
}

// ---------------- prep: fp32 -> fp16 (uint4 stores, 4 float4/thread) -------
__global__ void prep_all(const float* __restrict__ A, const float* __restrict__ B,
                         const float* __restrict__ gamma, const float* __restrict__ beta,
                         const float* __restrict__ W, const float* __restrict__ b) {
    if (blockIdx.x < 512) {
        // 524288 float4 total; 512 blocks x 256 threads x 2 iters x 2 float4
#pragma unroll
        for (int it = 0; it < 2; ++it) {
            const unsigned v2 = (blockIdx.x * 512 + it * 256 + threadIdx.x) * 2;
            const float4* src;
            __half* dh;
            unsigned i;
            if (v2 < 262144) { src = (const float4*)A; i = v2; dh = g_Ah; }
            else             { src = (const float4*)B; i = v2 - 262144; dh = g_Bh; }
            const float4 x0 = src[i];
            const float4 x1 = src[i + 1];
            __half2 a01 = __floats2half2_rn(x0.x, x0.y);
            __half2 a23 = __floats2half2_rn(x0.z, x0.w);
            __half2 b01 = __floats2half2_rn(x1.x, x1.y);
            __half2 b23 = __floats2half2_rn(x1.z, x1.w);
            uint4 o;
            o.x = *(uint32_t*)&a01;
            o.y = *(uint32_t*)&a23;
            o.z = *(uint32_t*)&b01;
            o.w = *(uint32_t*)&b23;
            ((uint4*)dh)[i >> 1] = o;
        }
    } else {
        const int o = blockIdx.x - 512;    // 128 blocks
        const int t = threadIdx.x;
        float s = 0.f;
        for (int k = t; k < KDIM; k += 256) {
            const float wv = W[o * KDIM + k];
            g_gWh[o * KDIM + k] = __float2half_rn(gamma[k] * wv);
            s += beta[k] * wv;
        }
        __shared__ float red[256];
        red[t] = s;
        __syncthreads();
        for (int st = 128; st > 0; st >>= 1) {
            if (t < st) red[t] += red[t + st];
            __syncthreads();
        }
        if (t == 0) g_cb[o] = b[o] + red[0];
    }
}

// ---------------- kernel A: GEMM1 + LN -> g_NpH (2 chunks of K=64) ---------
__global__ __launch_bounds__(256, 2)
void coevol_g1_kernel() {
    extern __shared__ char sm[];
    const uint32_t SB = smem_u32(sm);

    const int tid = threadIdx.x;
    const int lane = tid & 31, w = tid >> 5;
    const int bx = blockIdx.x, by = blockIdx.y;

    const int mbase = (w & 3) * 32;
    const int nbase = (w >> 2) * 64;
    float acc[2][8][4];
#pragma unroll
    for (int mt = 0; mt < 2; ++mt)
#pragma unroll
        for (int nt = 0; nt < 8; ++nt)
#pragma unroll
            for (int c = 0; c < 4; ++c) acc[mt][nt][c] = 0.f;

    const int g4 = lane >> 3;
    const int grow = lane & 7;
    const int kadd4 = (g4 >> 1) * 8, madd4 = (g4 & 1) * 8;
    const int kadd2 = (g4 & 1) * 8;

    // staging: 8 cp16/thread/stage. v: buf = v>>10 (AH,BH); r=(v&1023)>>4; c=v&15
    auto stage_load = [&](int ch) {
        const uint32_t stg = SB + (uint32_t)(ch & 1) * A_STAGE;
#pragma unroll
        for (int it = 0; it < 8; ++it) {
            const int v = it * 256 + tid;          // 0..2047
            const int buf = v >> 10;
            const int rem = v & 1023;
            const int r = rem >> 4, c = rem & 15;  // r 0..63
            const size_t srow = (size_t)(ch * 64 + r) * 16384;  // 8192 fp16/row
            const uint32_t dst = stg + (uint32_t)buf * 17408u
                               + (uint32_t)r * 272u + (uint32_t)c * 16u;
            const char* src = (buf == 0)
                ? (const char*)g_Ah + srow + bx * 256 + c * 16
                : (const char*)g_Bh + srow + by * 256 + c * 16;
            cp16(dst, src);
        }
    };

    stage_load(0); cp_commit();
    stage_load(1); cp_commit();

    for (int ch = 0; ch < 2; ++ch) {
        if (ch == 0) cp_wait<1>(); else cp_wait<0>();
        __syncthreads();

        const uint32_t stg = SB + (uint32_t)(ch & 1) * A_STAGE;
#pragma unroll
        for (int ks = 0; ks < 4; ++ks) {
            uint32_t ah[2][4];
#pragma unroll
            for (int mt = 0; mt < 2; ++mt) {
                const uint32_t aoff = (uint32_t)(ks * 16 + kadd4 + grow) * 272u
                                    + (uint32_t)(mbase + mt * 16 + madd4) * 2u;
                ldmx4t(ah[mt], stg + A_AH + aoff);
            }
#pragma unroll
            for (int nt = 0; nt < 8; ++nt) {
                uint32_t bh[2];
                const uint32_t boff = (uint32_t)(ks * 16 + kadd2 + grow) * 272u
                                    + (uint32_t)(nbase + nt * 8) * 2u;
                ldmx2t(bh, stg + A_BH + boff);
#pragma unroll
                for (int mt = 0; mt < 2; ++mt)
                    mma_f32(acc[mt][nt], ah[mt], bh);
            }
        }
        if (ch == 0) __syncthreads();  // all warps done with stage 0 reads
    }
    __syncthreads();  // stage smem reuse for Np staging

    // ---------------- LayerNorm (warp-local) -> Np smem fp16 ----------
    const int i_loc = w & 3;
#pragma unroll
    for (int lb = 0; lb < 2; ++lb) {
        const int l_loc = (w >> 2) * 2 + lb;
        float sum = 0.f, sq = 0.f;
#pragma unroll
        for (int mt = 0; mt < 2; ++mt)
#pragma unroll
            for (int nt4 = 0; nt4 < 4; ++nt4)
#pragma unroll
                for (int c = 0; c < 4; ++c) {
                    const float v = acc[mt][lb * 4 + nt4][c];
                    sum += v;
                    sq = fmaf(v, v, sq);
                }
#pragma unroll
        for (int off = 16; off >= 1; off >>= 1) {
            sum += __shfl_xor_sync(0xffffffffu, sum, off);
            sq  += __shfl_xor_sync(0xffffffffu, sq, off);
        }
        const float mean = sum * (1.f / KDIM);
        const float var  = sq * (1.f / KDIM) - mean * mean;
        const float rstd = rsqrtf(var + LN_EPS);
        const int p = i_loc * 4 + l_loc;
#pragma unroll
        for (int mt = 0; mt < 2; ++mt)
#pragma unroll
            for (int nt4 = 0; nt4 < 4; ++nt4)
#pragma unroll
                for (int cp = 0; cp < 2; ++cp) {
                    const float f0 = (acc[mt][lb * 4 + nt4][cp * 2 + 0] - mean) * rstd;
                    const float f1 = (acc[mt][lb * 4 + nt4][cp * 2 + 1] - mean) * rstd;
                    __half2 h2 = __floats2half2_rn(f0, f1);
                    const int j  = mt * 16 + (lane >> 2) + cp * 8;
                    const int mc = nt4 * 4 + (lane & 3);
                    const int idx = p * 516 + j * 16 + (mc ^ ((j & 3) << 2));
                    *(uint32_t*)(sm + OFF_NPH + idx * 4) = *(uint32_t*)&h2;
                }
    }
    __syncthreads();

    // ---------------- copy Np smem -> global (coalesced) ----------
#pragma unroll
    for (int it = 0; it < 8; ++it) {
        const int v = it * 256 + tid;          // 0..2047 uint4
        const int p = v >> 7;
        const int c4 = v & 127;
        const int wb = c4 * 4;
        const int j = wb >> 4, mc = wb & 15;
        const int sidx = p * 516 + j * 16 + (mc ^ ((j & 3) << 2));
        const uint32_t* s = (const uint32_t*)(sm + OFF_NPH) + sidx;
        uint4 val = make_uint4(s[0], s[1], s[2], s[3]);
        const int gi = bx * 4 + (p >> 2);
        const int gl = by * 4 + (p & 3);
        const size_t pair = (size_t)gi * SEQ_L + gl;
        ((uint4*)g_NpH)[pair * 128 + c4] = val;
    }
}

// ---------------- kernel B: out = NpH . gWh + cb (3-stage cp.async) --------
// Grid 512: CTA = 128 pairs x 128 o, K = 1024 in 16 chunks of 64.
__global__ __launch_bounds__(256, 2)
void coevol_g2_kernel(float* __restrict__ out) {
    extern __shared__ char sm[];
    const uint32_t SB = smem_u32(sm);

    const int tid = threadIdx.x;
    const int lane = tid & 31, w = tid >> 5;
    const int pb = blockIdx.x;

    const int mp = (w & 3) * 32;
    const int ob = (w >> 2) * 64;

    float acc[2][8][4];
#pragma unroll
    for (int mt = 0; mt < 2; ++mt)
#pragma unroll
        for (int nt = 0; nt < 8; ++nt)
#pragma unroll
            for (int c = 0; c < 4; ++c) acc[mt][nt][c] = 0.f;

    const int rA = lane & 15, cAs = lane >> 4;
    const int rB = ((lane >> 4) << 3) + (lane & 7);
    const int cBs = (lane >> 3) & 1;

    // stage load: 8 cp16/thread. Np and gW rows 128 B, swizzle c^(r&7).
    auto stage_load = [&](int ch) {
        const uint32_t stg = SB + (uint32_t)(ch % 3) * B_STAGE;
#pragma unroll
        for (int it = 0; it < 8; ++it) {
            const int v = it * 256 + tid;     // 0..2047
            const int buf = v >> 10;          // 0 = Np, 1 = gW
            const int rem = v & 1023;
            const int r = rem >> 3, c = rem & 7;
            const uint32_t dst = stg + (uint32_t)buf * 16384u
                               + (uint32_t)(r * 128) + (uint32_t)((c ^ (r & 7)) << 4);
            const char* src = (buf == 0)
                ? (const char*)g_NpH + (size_t)(pb * 128 + r) * 2048 + ch * 128 + c * 16
                : (const char*)g_gWh + (size_t)r * 2048 + ch * 128 + c * 16;
            cp16(dst, src);
        }
    };

    stage_load(0); cp_commit();
    stage_load(1); cp_commit();

    for (int ch = 0; ch < 16; ++ch) {
        if (ch < 15) cp_wait<1>(); else cp_wait<0>();
        __syncthreads();
        if (ch + 2 < 16) { stage_load(ch + 2); cp_commit(); }

        const uint32_t stg = SB + (uint32_t)(ch % 3) * B_STAGE;
#pragma unroll
        for (int ks = 0; ks < 4; ++ks) {
            const int cc = ks * 2;
            uint32_t ah[2][4];
#pragma unroll
            for (int mt = 0; mt < 2; ++mt) {
                const int r = mp + mt * 16 + rA;
                const int c = cc + cAs;
                ldmx4(ah[mt], stg + S_N
                      + (uint32_t)(r * 128 + ((c ^ (r & 7)) << 4)));
            }
#pragma unroll
            for (int n4 = 0; n4 < 4; ++n4) {
                uint32_t bh[4];
                const int r = ob + n4 * 16 + rB;
                const int c = cc + cBs;
                ldmx4(bh, stg + S_G
                      + (uint32_t)(r * 128 + ((c ^ (r & 7)) << 4)));
#pragma unroll
                for (int half = 0; half < 2; ++half) {
                    const int nt = n4 * 2 + half;
#pragma unroll
                    for (int mt = 0; mt < 2; ++mt)
                        mma_f32(acc[mt][nt], ah[mt], bh + half * 2);
                }
            }
        }
    }

    // ---------------- epilogue ----------------
#pragma unroll
    for (int nt = 0; nt < 8; ++nt) {
        const int o0 = ob + nt * 8 + 2 * (lane & 3);
        const float cb0 = g_cb[o0], cb1 = g_cb[o0 + 1];
#pragma unroll
        for (int mt = 0; mt < 2; ++mt) {
            const int r0 = mp + mt * 16 + (lane >> 2);
            const size_t pair0 = (size_t)pb * 128 + r0;
            float2 v0, v1;
            v0.x = acc[mt][nt][0] + cb0;
            v0.y = acc[mt][nt][1] + cb1;
            v1.x = acc[mt][nt][2] + cb0;
            v1.y = acc[mt][nt][3] + cb1;
            *(float2*)&out[pair0 * NOUT + o0] = v0;
            *(float2*)&out[(pair0 + 8) * NOUT + o0] = v1;
        }
    }
}

// ---------------------------------------------------------------------------
extern "C" void kernel_launch(void* const* d_in, const int* in_sizes, int n_in,
                              void* d_out, int out_size) {
    const float* x_down   = (const float*)d_in[0];
    const float* x_down_w = (const float*)d_in[1];
    const float* gamma    = (const float*)d_in[2];
    const float* beta     = (const float*)d_in[3];
    const float* W        = (const float*)d_in[4];
    const float* b        = (const float*)d_in[5];
    float* out = (float*)d_out;

    cudaFuncSetAttribute(coevol_g1_kernel,
                         cudaFuncAttributeMaxDynamicSharedMemorySize, SMEM_A_TOTAL);
    cudaFuncSetAttribute(coevol_g2_kernel,
                         cudaFuncAttributeMaxDynamicSharedMemorySize, SMEM_B_TOTAL);

    prep_all<<<640, 256>>>(x_down, x_down_w, gamma, beta, W, b);

    dim3 grid1(SEQ_L / 4, SEQ_L / 4);  // 64 x 64
    coevol_g1_kernel<<<grid1, 256, SMEM_A_TOTAL>>>();

    coevol_g2_kernel<<<512, 256, SMEM_B_TOTAL>>>(out);
}